// round 17
// baseline (speedup 1.0000x reference)
#include <cuda_runtime.h>
#include <cuda_bf16.h>
#include <cstdint>

#define BB 16384
#define TT 16
#define II 256
#define HH 128
#define GG 512
#define EPSF 1e-5f
#define NT 256

// ---------------- scratch (device globals: allocation-free) ----------------
__device__ __align__(16) __nv_bfloat16 g_wih_hi[GG * II], g_wih_lo[GG * II];
__device__ __align__(16) __nv_bfloat16 g_whh_hi[GG * HH], g_whh_lo[GG * HH];

// ---------------- helpers ----------------
__device__ __forceinline__ uint32_t smem_u32(const void* p) {
    uint32_t a;
    asm("{ .reg .u64 t; cvta.to.shared.u64 t, %1; cvt.u32.u64 %0, t; }" : "=r"(a) : "l"(p));
    return a;
}
__device__ __forceinline__ void ldsm4(uint32_t* r, uint32_t a) {
    asm volatile("ldmatrix.sync.aligned.m8n8.x4.shared.b16 {%0,%1,%2,%3}, [%4];"
                 : "=r"(r[0]), "=r"(r[1]), "=r"(r[2]), "=r"(r[3]) : "r"(a));
}
__device__ __forceinline__ void mma16816(float* d, const uint32_t* a, uint32_t b0, uint32_t b1) {
    asm volatile(
        "mma.sync.aligned.m16n8k16.row.col.f32.bf16.bf16.f32 "
        "{%0,%1,%2,%3},{%4,%5,%6,%7},{%8,%9},{%0,%1,%2,%3};"
        : "+f"(d[0]), "+f"(d[1]), "+f"(d[2]), "+f"(d[3])
        : "r"(a[0]), "r"(a[1]), "r"(a[2]), "r"(a[3]), "r"(b0), "r"(b1));
}
#define CPA16(s, g) \
    asm volatile("cp.async.cg.shared.global [%0], [%1], 16;" \
                 :: "r"(s), "l"(__cvta_generic_to_global(g)) : "memory")
#define CP_COMMIT() asm volatile("cp.async.commit_group;" ::: "memory")
#define CP_WAIT0()  asm volatile("cp.async.wait_group 0;" ::: "memory")

__device__ __forceinline__ float qsum(float v) {
    v += __shfl_xor_sync(0xffffffffu, v, 1);
    v += __shfl_xor_sync(0xffffffffu, v, 2);
    return v;
}
__device__ __forceinline__ float sigm(float x) {
    return __fdividef(1.f, 1.f + __expf(-x));
}
__device__ __forceinline__ float tanh_fast(float x) {
    float xc = fminf(fmaxf(x, -9.f), 9.f);
    float e = __expf(2.f * xc);
    return __fdividef(e - 1.f, e + 1.f);
}
__device__ __forceinline__ uint32_t pack2(__nv_bfloat16 lo, __nv_bfloat16 hi) {
    return (uint32_t)__bfloat16_as_ushort(lo) | ((uint32_t)__bfloat16_as_ushort(hi) << 16);
}

// ---------------- smem layout (bytes) ----------------
// x tile hi/lo [64 rows][264 bf16 = 528 B]; h tile hi/lo [64][136 bf16 = 272 B];
// B chunk ring 2x[128 n][136 bf16 = 272 B]; red float2[384]; const floats[2304]
#define XA_HI 0
#define XA_LO 33792
#define HA_HI 67584
#define HA_LO 84992
#define MB0   102400
#define MB1   137216
#define SRED  172032
#define SCON  175104
#define SMEM_TOT 184320

// ---------------- splitters (fp32 -> bf16 hi + bf16 residual) ----------------
extern "C" __global__ void split_wih(const float* __restrict__ s) {
    int i = blockIdx.x * blockDim.x + threadIdx.x;
    if (i < GG * II) {
        float v = s[i];
        __nv_bfloat16 h = __float2bfloat16(v);
        g_wih_hi[i] = h;
        g_wih_lo[i] = __float2bfloat16(v - __bfloat162float(h));
    }
}
extern "C" __global__ void split_whh(const float* __restrict__ s) {
    int i = blockIdx.x * blockDim.x + threadIdx.x;
    if (i < GG * HH) {
        float v = s[i];
        __nv_bfloat16 h = __float2bfloat16(v);
        g_whh_hi[i] = h;
        g_whh_lo[i] = __float2bfloat16(v - __bfloat162float(h));
    }
}

// ---------------- chunk issue ----------------
// global chunk index pc in [0, 384): phase = pc/6, c = pc%6
// c: 0,1 = W_ih hi (K halves); 2,3 = W_ih lo; 4 = W_hh hi; 5 = W_hh lo
__device__ __forceinline__ void issue_chunk(uint32_t sb, int tid, int pc) {
    const int c = pc % 6;
    const int ph = pc / 6;
    const int gq = (0x3120 >> ((ph & 3) * 4)) & 0xF;
    const __nv_bfloat16* src;
    int koff, stride;
    if (c < 2)       { src = g_wih_hi; koff = c * 128;       stride = II; }
    else if (c < 4)  { src = g_wih_lo; koff = (c - 2) * 128; stride = II; }
    else if (c == 4) { src = g_whh_hi; koff = 0;             stride = HH; }
    else             { src = g_whh_lo; koff = 0;             stride = HH; }
    const uint32_t slot = sb + ((pc & 1) ? MB1 : MB0);
#pragma unroll
    for (int it = 0; it < 8; ++it) {
        int ci = tid + it * NT;                 // 2048 transfers of 16 B
        int n = ci >> 4, k8 = (ci & 15) * 8;
        CPA16(slot + n * 272 + k8 * 2,
              src + (size_t)(gq * HH + n) * stride + koff + k8);
    }
    CP_COMMIT();
}

// ---------------- merged kernel: proj + 16 LN-LSTM steps ----------------
extern "C" __global__ void __launch_bounds__(NT, 1)
merged_kernel(const float* __restrict__ x,
              const float* __restrict__ gx, const float* __restrict__ bx,
              const float* __restrict__ gh, const float* __restrict__ bh,
              const float* __restrict__ gc, const float* __restrict__ bc,
              const float* __restrict__ bias,
              const float* __restrict__ h0, const float* __restrict__ c0,
              float* __restrict__ out, int write_hn)
{
    extern __shared__ char smc[];
    const uint32_t sb = smem_u32(smc);
    const int tid = threadIdx.x, lane = tid & 31, wid = tid >> 5;
    const int m0 = blockIdx.x * 64;
    const int wr0 = (wid >> 1) * 16;
    const int half = wid & 1, cb = half * 64;
    float2* red2 = (float2*)(smc + SRED);
    float* con = (float*)(smc + SCON);

    issue_chunk(sb, tid, 0);                    // first W_ih chunk in flight

    // h0 -> HA tiles (bf16 hi/lo)
#pragma unroll
    for (int it = 0; it < 8; ++it) {
        int ci = tid + it * NT;
        int row = ci >> 5, c4 = (ci & 31) * 4;
        float4 v = *(const float4*)(h0 + (size_t)(m0 + row) * HH + c4);
        __nv_bfloat16 b0 = __float2bfloat16(v.x), b1 = __float2bfloat16(v.y);
        __nv_bfloat16 b2 = __float2bfloat16(v.z), b3 = __float2bfloat16(v.w);
        uint2 hp, lp;
        hp.x = pack2(b0, b1); hp.y = pack2(b2, b3);
        lp.x = pack2(__float2bfloat16(v.x - __bfloat162float(b0)),
                     __float2bfloat16(v.y - __bfloat162float(b1)));
        lp.y = pack2(__float2bfloat16(v.z - __bfloat162float(b2)),
                     __float2bfloat16(v.w - __bfloat162float(b3)));
        *(uint2*)(smc + HA_HI + row * 272 + c4 * 2) = hp;
        *(uint2*)(smc + HA_LO + row * 272 + c4 * 2) = lp;
    }
    // constants -> smem
#pragma unroll
    for (int it = 0; it < 2; ++it) {
        int idx = tid + it * NT;                // 512
        con[idx]        = gx[idx];
        con[512 + idx]  = bx[idx] + bias[idx];
        con[1024 + idx] = gh[idx];
        con[1536 + idx] = bh[idx];
    }
    if (tid < 128) { con[2048 + tid] = gc[tid]; con[2176 + tid] = bc[tid]; }

    const int rA = wr0 + (lane >> 2), rB = rA + 8;
    const size_t bidxA = (size_t)m0 + rA, bidxB = bidxA + 8;
    const int q2 = 2 * (lane & 3);

    float C[8][4];
#pragma unroll
    for (int j = 0; j < 8; ++j) {
        float2 va = *(const float2*)(c0 + bidxA * HH + cb + 8 * j + q2);
        float2 vb = *(const float2*)(c0 + bidxB * HH + cb + 8 * j + q2);
        C[j][0] = va.x; C[j][1] = va.y; C[j][2] = vb.x; C[j][3] = vb.y;
    }

    const uint32_t bfo = (cb + (lane & 7) + ((lane >> 4) << 3)) * 272 + (((lane >> 3) & 1) << 4);

    float accx[8][4], acch[8][4], S[8][4];
    float sc0, qc0, sc1, qc1;

#pragma unroll 1
    for (int t = 0; t < TT; ++t) {
        sc0 = 0.f; qc0 = 0.f; sc1 = 0.f; qc1 = 0.f;
#pragma unroll 1
        for (int p = 0; p < 4; ++p) {
            const int gq = (0x3120 >> (p * 4)) & 0xF;   // i(0), g(2), f(1), o(3)
            const int pcb = (t * 4 + p) * 6;
#pragma unroll
            for (int j = 0; j < 8; ++j) {
                accx[j][0] = accx[j][1] = accx[j][2] = accx[j][3] = 0.f;
                acch[j][0] = acch[j][1] = acch[j][2] = acch[j][3] = 0.f;
            }
#pragma unroll 1
            for (int c = 0; c < 6; ++c) {
                const int pc = pcb + c;
                CP_WAIT0();
                __syncthreads();                // chunk pc visible; slot pc^1 free
                if (pc + 1 < 4 * TT * 6) issue_chunk(sb, tid, pc + 1);

                if (p == 0 && c == 0) {
                    // stage x(t) -> XA tiles (hi/lo)
#pragma unroll
                    for (int it = 0; it < 16; ++it) {
                        int ci = tid + it * NT;
                        int row = ci >> 6, c4 = (ci & 63) * 4;
                        float4 v = *(const float4*)(x + ((size_t)(m0 + row) * TT + t) * II + c4);
                        __nv_bfloat16 b0 = __float2bfloat16(v.x), b1 = __float2bfloat16(v.y);
                        __nv_bfloat16 b2 = __float2bfloat16(v.z), b3 = __float2bfloat16(v.w);
                        uint2 hp, lp;
                        hp.x = pack2(b0, b1); hp.y = pack2(b2, b3);
                        lp.x = pack2(__float2bfloat16(v.x - __bfloat162float(b0)),
                                     __float2bfloat16(v.y - __bfloat162float(b1)));
                        lp.y = pack2(__float2bfloat16(v.z - __bfloat162float(b2)),
                                     __float2bfloat16(v.w - __bfloat162float(b3)));
                        *(uint2*)(smc + XA_HI + row * 528 + c4 * 2) = hp;
                        *(uint2*)(smc + XA_LO + row * 528 + c4 * 2) = lp;
                    }
                    __syncthreads();
                }

                const uint32_t bb = sb + ((pc & 1) ? MB1 : MB0) + bfo;
                const bool xside = (c < 4);
                const bool twop = (c < 2) || (c == 4);
                const uint32_t abase = xside
                    ? (sb + XA_HI + (wr0 + (lane & 15)) * 528 + ((c & 1) << 8) + ((lane >> 4) << 4))
                    : (sb + HA_HI + (wr0 + (lane & 15)) * 272 + ((lane >> 4) << 4));
                const uint32_t adel = xside ? (XA_LO - XA_HI) : (HA_LO - HA_HI);

                auto mma_chunk = [&](float (&ACC)[8][4]) {
#pragma unroll
                    for (int ks = 0; ks < 8; ++ks) {
                        uint32_t ah[4], al[4];
                        ldsm4(ah, abase + ks * 32);
                        if (twop) ldsm4(al, abase + ks * 32 + adel);
#pragma unroll
                        for (int g = 0; g < 4; ++g) {
                            uint32_t b4[4];
                            ldsm4(b4, bb + g * 16 * 272 + ks * 32);
                            mma16816(ACC[2 * g],     ah, b4[0], b4[1]);
                            mma16816(ACC[2 * g + 1], ah, b4[2], b4[3]);
                            if (twop) {
                                mma16816(ACC[2 * g],     al, b4[0], b4[1]);
                                mma16816(ACC[2 * g + 1], al, b4[2], b4[3]);
                            }
                        }
                    }
                };
                if (xside) mma_chunk(accx); else mma_chunk(acch);
            }

            // ---- phase epilogue: LN_x and LN_h (one combined red exchange) ----
            float sx0 = 0.f, qx0 = 0.f, sx1 = 0.f, qx1 = 0.f;
            float sh0 = 0.f, qh0 = 0.f, sh1 = 0.f, qh1 = 0.f;
#pragma unroll
            for (int j = 0; j < 8; ++j) {
                sx0 += accx[j][0] + accx[j][1]; qx0 += accx[j][0] * accx[j][0] + accx[j][1] * accx[j][1];
                sx1 += accx[j][2] + accx[j][3]; qx1 += accx[j][2] * accx[j][2] + accx[j][3] * accx[j][3];
                sh0 += acch[j][0] + acch[j][1]; qh0 += acch[j][0] * acch[j][0] + acch[j][1] * acch[j][1];
                sh1 += acch[j][2] + acch[j][3]; qh1 += acch[j][2] * acch[j][2] + acch[j][3] * acch[j][3];
            }
            sx0 = qsum(sx0); qx0 = qsum(qx0); sx1 = qsum(sx1); qx1 = qsum(qx1);
            sh0 = qsum(sh0); qh0 = qsum(qh0); sh1 = qsum(sh1); qh1 = qsum(qh1);
            if ((lane & 3) == 0) {
                red2[rA * 2 + half]       = make_float2(sx0, qx0);
                red2[rB * 2 + half]       = make_float2(sx1, qx1);
                red2[128 + rA * 2 + half] = make_float2(sh0, qh0);
                red2[128 + rB * 2 + half] = make_float2(sh1, qh1);
            }
            __syncthreads();
            {
                float2 o;
                o = red2[rA * 2 + (1 - half)];       sx0 += o.x; qx0 += o.y;
                o = red2[rB * 2 + (1 - half)];       sx1 += o.x; qx1 += o.y;
                o = red2[128 + rA * 2 + (1 - half)]; sh0 += o.x; qh0 += o.y;
                o = red2[128 + rB * 2 + (1 - half)]; sh1 += o.x; qh1 += o.y;
            }
            const float mx0 = sx0 * (1.f / HH), rx0 = rsqrtf(qx0 * (1.f / HH) - mx0 * mx0 + EPSF);
            const float mx1 = sx1 * (1.f / HH), rx1 = rsqrtf(qx1 * (1.f / HH) - mx1 * mx1 + EPSF);
            const float mh0 = sh0 * (1.f / HH), rh0 = rsqrtf(qh0 * (1.f / HH) - mh0 * mh0 + EPSF);
            const float mh1 = sh1 * (1.f / HH), rh1 = rsqrtf(qh1 * (1.f / HH) - mh1 * mh1 + EPSF);

#pragma unroll
            for (int j = 0; j < 8; ++j) {
                int colb = cb + 8 * j + q2;
                int gcol = gq * HH + colb;
                float2 vgx = *(const float2*)(con + gcol);
                float2 vcb = *(const float2*)(con + 512 + gcol);
                float2 vgh = *(const float2*)(con + 1024 + gcol);
                float2 vbh = *(const float2*)(con + 1536 + gcol);
#pragma unroll
                for (int e = 0; e < 4; ++e) {
                    float mx = (e < 2) ? mx0 : mx1, rx = (e < 2) ? rx0 : rx1;
                    float mh = (e < 2) ? mh0 : mh1, rh = (e < 2) ? rh0 : rh1;
                    float gxe = (e & 1) ? vgx.y : vgx.x;
                    float cbe = (e & 1) ? vcb.y : vcb.x;
                    float ghe = (e & 1) ? vgh.y : vgh.x;
                    float bhe = (e & 1) ? vbh.y : vbh.x;
                    float a  = (accx[j][e] - mx) * rx * gxe + cbe;
                    float gn = a + (acch[j][e] - mh) * rh * ghe + bhe;
                    if (p == 0) {
                        S[j][e] = sigm(gn);
                    } else if (p == 1) {
                        S[j][e] *= tanh_fast(gn);
                    } else if (p == 2) {
                        float cv = sigm(gn) * C[j][e] + S[j][e];
                        C[j][e] = cv;
                        if (e < 2) { sc0 += cv; qc0 += cv * cv; }
                        else       { sc1 += cv; qc1 += cv * cv; }
                    } else {
                        accx[j][e] = sigm(gn);          // sigma(o)
                    }
                }
            }
        }

        // ---- cell-LN + outputs + h writeback ----
        sc0 = qsum(sc0); qc0 = qsum(qc0); sc1 = qsum(sc1); qc1 = qsum(qc1);
        if ((lane & 3) == 0) {
            red2[256 + rA * 2 + half] = make_float2(sc0, qc0);
            red2[256 + rB * 2 + half] = make_float2(sc1, qc1);
        }
        __syncthreads();
        {
            float2 o;
            o = red2[256 + rA * 2 + (1 - half)]; sc0 += o.x; qc0 += o.y;
            o = red2[256 + rB * 2 + (1 - half)]; sc1 += o.x; qc1 += o.y;
        }
        const float mc0 = sc0 * (1.f / HH), rc0 = rsqrtf(qc0 * (1.f / HH) - mc0 * mc0 + EPSF);
        const float mc1 = sc1 * (1.f / HH), rc1 = rsqrtf(qc1 * (1.f / HH) - mc1 * mc1 + EPSF);
        float* oA = out + (bidxA * TT + t) * HH;
        float* oB = out + (bidxB * TT + t) * HH;
#pragma unroll
        for (int j = 0; j < 8; ++j) {
            int colb = cb + 8 * j + q2;
            float2 gc2 = *(const float2*)(con + 2048 + colb);
            float2 bc2 = *(const float2*)(con + 2176 + colb);
            float hv[4];
#pragma unroll
            for (int e = 0; e < 4; ++e) {
                float mc = (e < 2) ? mc0 : mc1, rc = (e < 2) ? rc0 : rc1;
                float gv = (e & 1) ? gc2.y : gc2.x;
                float bv = (e & 1) ? bc2.y : bc2.x;
                float cl = (C[j][e] - mc) * rc * gv + bv;
                hv[e] = accx[j][e] * tanh_fast(cl);
            }
            *(float2*)(oA + colb) = make_float2(hv[0], hv[1]);
            *(float2*)(oB + colb) = make_float2(hv[2], hv[3]);
            if (write_hn && t == TT - 1) {
                *(float2*)(out + (size_t)BB * TT * HH + bidxA * HH + colb) = make_float2(hv[0], hv[1]);
                *(float2*)(out + (size_t)BB * TT * HH + bidxB * HH + colb) = make_float2(hv[2], hv[3]);
            }
            __nv_bfloat16 b0 = __float2bfloat16(hv[0]), b1 = __float2bfloat16(hv[1]);
            __nv_bfloat16 b2 = __float2bfloat16(hv[2]), b3 = __float2bfloat16(hv[3]);
            *(uint32_t*)(smc + HA_HI + rA * 272 + colb * 2) = pack2(b0, b1);
            *(uint32_t*)(smc + HA_HI + rB * 272 + colb * 2) = pack2(b2, b3);
            *(uint32_t*)(smc + HA_LO + rA * 272 + colb * 2) =
                pack2(__float2bfloat16(hv[0] - __bfloat162float(b0)),
                      __float2bfloat16(hv[1] - __bfloat162float(b1)));
            *(uint32_t*)(smc + HA_LO + rB * 272 + colb * 2) =
                pack2(__float2bfloat16(hv[2] - __bfloat162float(b2)),
                      __float2bfloat16(hv[3] - __bfloat162float(b3)));
        }
        // next phase's chunk __syncthreads orders HA stores before ldsm reads
    }
}

// ---------------- host ----------------
extern "C" void kernel_launch(void* const* d_in, const int* in_sizes, int n_in,
                              void* d_out, int out_size)
{
    const float* x    = (const float*)d_in[0];
    const float* h0   = (const float*)d_in[1];
    const float* c0   = (const float*)d_in[2];
    const float* W_ih = (const float*)d_in[3];
    const float* W_hh = (const float*)d_in[4];
    const float* bias = (const float*)d_in[5];
    const float* g_x  = (const float*)d_in[6];
    const float* b_x  = (const float*)d_in[7];
    const float* gh   = (const float*)d_in[8];
    const float* bh   = (const float*)d_in[9];
    const float* gc   = (const float*)d_in[10];
    const float* bc   = (const float*)d_in[11];
    float* out = (float*)d_out;

    cudaFuncSetAttribute(merged_kernel, cudaFuncAttributeMaxDynamicSharedMemorySize, SMEM_TOT);

    split_wih<<<(GG * II + 255) / 256, 256>>>(W_ih);
    split_whh<<<(GG * HH + 255) / 256, 256>>>(W_hh);

    const long long need = (long long)BB * TT * HH + (long long)BB * HH;
    const int write_full = (out_size >= need) ? 1 : 0;

    merged_kernel<<<BB / 64, NT, SMEM_TOT>>>(x, g_x, b_x, gh, bh, gc, bc, bias,
                                             h0, c0, out, write_full);
}